// round 1
// baseline (speedup 1.0000x reference)
#include <cuda_runtime.h>
#include <cstdint>

#define MAXN 16384
#define RUN  512

// ---------------- scratch (device globals: no allocations allowed) ----------
__device__ float              g_mind[MAXN];
__device__ int                g_counts[MAXN];
__device__ float4             g_farpos[MAXN];
__device__ int                g_faridx[MAXN];
__device__ int                g_nfar;
__device__ int                g_maxcount;
__device__ unsigned long long g_keys[MAXN];
__device__ unsigned long long g_runsA[MAXN];
__device__ unsigned long long g_runsB[MAXN];

// bond table: default 1.0, overrides per reference dict
__constant__ float c_bond[20] = {
    1.05f, 1.3f, 1.1f, 1.2f, 1.0f, 1.1f, 1.2f, 1.0f, 1.4f, 1.0f,
    1.0f,  1.3f, 1.0f, 1.5f, 1.0f, 1.05f, 1.05f, 1.6f, 1.4f, 1.1f
};

// ---------------- k0: reset run-to-run state (graph replays) ----------------
__global__ void k_init() {
    g_nfar = 0;
    g_maxcount = 0;
}

// ---------------- k1: min dist to ligand, classify, compact far atoms -------
__global__ void k_mind(const float* __restrict__ pos,
                       const float* __restrict__ lig,
                       int N, int M) {
    __shared__ float s_lig[3 * 256];
    for (int t = threadIdx.x; t < M * 3; t += blockDim.x) s_lig[t] = lig[t];
    __syncthreads();

    int i = blockIdx.x * blockDim.x + threadIdx.x;
    if (i >= N) return;

    float px = pos[3 * i + 0], py = pos[3 * i + 1], pz = pos[3 * i + 2];
    float best = 3.4e38f;
    for (int m = 0; m < M; m++) {
        float dx = px - s_lig[3 * m + 0];
        float dy = py - s_lig[3 * m + 1];
        float dz = pz - s_lig[3 * m + 2];
        float d2 = dx * dx + dy * dy + dz * dz;
        best = fminf(best, d2);
    }
    float d = sqrtf(fmaxf(best, 1e-12f));
    g_mind[i]   = d;
    g_counts[i] = 0;

    if (d > 8.0f) {
        int slot = atomicAdd(&g_nfar, 1);
        g_farpos[slot] = make_float4(px, py, pz, 0.0f);
        g_faridx[slot] = i;
    }
}

// ---------------- k2: far x far neighbor counts (tiled smem) ----------------
__global__ void k_counts() {
    int nfar = g_nfar;
    if ((int)(blockIdx.x * blockDim.x) >= nfar) return;   // uniform per block

    int t = blockIdx.x * blockDim.x + threadIdx.x;
    bool active = t < nfar;
    float px = 0.f, py = 0.f, pz = 0.f;
    if (active) {
        float4 p = g_farpos[t];
        px = p.x; py = p.y; pz = p.z;
    }

    __shared__ float4 tile[256];
    int cnt = 0;
    for (int base = 0; base < nfar; base += 256) {
        int j = base + threadIdx.x;
        if (j < nfar) tile[threadIdx.x] = g_farpos[j];
        __syncthreads();
        int lim = min(256, nfar - base);
        if (active) {
            #pragma unroll 4
            for (int jj = 0; jj < lim; jj++) {
                float4 q = tile[jj];
                float dx = px - q.x, dy = py - q.y, dz = pz - q.z;
                float d2 = dx * dx + dy * dy + dz * dz;
                cnt += (d2 < 25.0f && d2 > 0.0f) ? 1 : 0;
            }
        }
        __syncthreads();
    }
    if (active) g_counts[g_faridx[t]] = cnt;
}

// ---------------- k3: max neighbor count -------------------------------------
__global__ void k_max(int N) {
    int i = blockIdx.x * blockDim.x + threadIdx.x;
    int v = (i < N) ? g_counts[i] : 0;
    #pragma unroll
    for (int o = 16; o > 0; o >>= 1)
        v = max(v, __shfl_down_sync(0xffffffffu, v, o));
    if ((threadIdx.x & 31) == 0) atomicMax(&g_maxcount, v);
}

// ---------------- k4: final scores + packed sort keys ------------------------
__global__ void k_score(const float* __restrict__ x,
                        float* __restrict__ out, int N, int F) {
    int i = blockIdx.x * blockDim.x + threadIdx.x;
    if (i >= N) return;

    float d = g_mind[i];
    float s;
    if (d <= 3.5f) {
        s = 10.0f;
    } else if (d <= 8.0f) {
        s = 5.0f * (8.0f - d) / 8.0f;
    } else {
        float mx = (float)g_maxcount;
        mx = (mx > 0.0f) ? mx : 1.0f;
        s = 1.0f - (float)g_counts[i] / (mx + 1e-6f);
    }
    int rt = (int)x[i * F + 1];
    rt = min(max(rt, 0), 19);
    s *= c_bond[rt];

    out[i] = s;

    unsigned int b = __float_as_uint(s);
    unsigned int u = b ^ ((b >> 31) ? 0xFFFFFFFFu : 0x80000000u);  // order-preserving
    g_keys[i] = ((unsigned long long)u << 32) | (unsigned long long)(0xFFFFFFFFu - (unsigned)i);
}

// ---------------- k5: per-block bitonic sort of 512 (descending) -------------
__global__ void k_sort512(int N) {
    __shared__ unsigned long long s[RUN];
    int t = threadIdx.x;
    int g = blockIdx.x * RUN + t;
    s[t] = (g < N) ? g_keys[g] : 0ULL;   // 0 is a safe minimum (real keys have MSB set)
    __syncthreads();

    for (int k = 2; k <= RUN; k <<= 1) {
        for (int j = k >> 1; j > 0; j >>= 1) {
            int ixj = t ^ j;
            if (ixj > t) {
                unsigned long long a = s[t], c = s[ixj];
                bool descRegion = ((t & k) == 0);
                if (descRegion ? (a < c) : (a > c)) { s[t] = c; s[ixj] = a; }
            }
            __syncthreads();
        }
    }
    g_runsA[blockIdx.x * RUN + t] = s[t];
}

// ---------------- k6: merge two desc runs of 512, keep top 512 ---------------
__global__ void k_merge(int srcIsA) {
    const unsigned long long* src = srcIsA ? g_runsA : g_runsB;
    unsigned long long*       dst = srcIsA ? g_runsB : g_runsA;

    __shared__ unsigned long long s[2 * RUN];
    int t = threadIdx.x;
    int b = blockIdx.x;
    s[t]       = src[(2 * b)     * RUN + t];
    s[RUN + t] = src[(2 * b + 1) * RUN + (RUN - 1 - t)];  // reversed -> bitonic
    __syncthreads();

    for (int j = RUN; j > 0; j >>= 1) {
        int i = ((t & ~(j - 1)) << 1) | (t & (j - 1));
        int p = i | j;
        unsigned long long a = s[i], c = s[p];
        if (a < c) { s[i] = c; s[p] = a; }
        __syncthreads();
    }
    dst[b * RUN + t] = s[t];
}

// ---------------- k7: unpack and write top-K scores + indices ----------------
__global__ void k_write(int finalInA, float* __restrict__ out, int N, int K) {
    const unsigned long long* run = finalInA ? g_runsA : g_runsB;
    int t = blockIdx.x * blockDim.x + threadIdx.x;
    if (t >= K) return;
    unsigned long long key = run[t];
    unsigned int u = (unsigned int)(key >> 32);
    unsigned int b = (u >> 31) ? (u ^ 0x80000000u) : (~u);
    float sc = __uint_as_float(b);
    unsigned int idx = 0xFFFFFFFFu - (unsigned int)(key & 0xFFFFFFFFull);
    out[N + t]     = sc;
    out[N + K + t] = (float)idx;
}

// ---------------- launch ------------------------------------------------------
extern "C" void kernel_launch(void* const* d_in, const int* in_sizes, int n_in,
                              void* d_out, int out_size) {
    const float* pos = (const float*)d_in[0];
    const float* lig = (const float*)d_in[1];
    const float* x   = (const float*)d_in[2];
    int N = in_sizes[0] / 3;          // 16384
    int M = in_sizes[1] / 3;          // 64
    int F = in_sizes[2] / N;          // 16
    int K = (out_size - N) / 2;       // 512 (scores[N] + top[K] + idx[K])
    float* out = (float*)d_out;

    k_init<<<1, 1>>>();
    k_mind<<<(N + 255) / 256, 256>>>(pos, lig, N, M);
    k_counts<<<(N + 255) / 256, 256>>>();
    k_max<<<(N + 255) / 256, 256>>>(N);
    k_score<<<(N + 255) / 256, 256>>>(x, out, N, F);

    int runs = (N + RUN - 1) / RUN;   // 32
    k_sort512<<<runs, RUN>>>(N);

    int srcA = 1;
    while (runs > 1) {
        k_merge<<<runs / 2, RUN>>>(srcA);
        srcA ^= 1;
        runs >>= 1;
    }
    k_write<<<(K + 255) / 256, 256>>>(srcA, out, N, K);
}

// round 2
// speedup vs baseline: 5.2011x; 5.2011x over previous
#include <cuda_runtime.h>
#include <cstdint>

#define MAXN   16384
#define RUN    512
#define NCELL  512           // 8x8x8 cells of 5 Angstrom
#define NB_CAP 2560          // smem neighborhood capacity (float4) = 40KB

// ---------------- scratch (device globals: no allocations allowed) ----------
__device__ float              g_mind[MAXN];
__device__ int                g_counts[MAXN];     // only far atoms' entries valid
__device__ float4             g_farpos[MAXN];     // compacted far atoms (unsorted)
__device__ int                g_faridx[MAXN];
__device__ int                g_farcell[MAXN];
__device__ float4             g_spos[MAXN];       // cell-sorted far atoms
__device__ int                g_sidx[MAXN];
__device__ int                g_nfar;
__device__ int                g_maxcount;
__device__ int                g_cellcnt[NCELL];
__device__ int                g_cellstart[NCELL + 1];
__device__ int                g_cellfill[NCELL];
__device__ unsigned long long g_keys[MAXN];
__device__ unsigned long long g_runsA[MAXN];
__device__ unsigned long long g_runsB[MAXN];

__constant__ float c_bond[20] = {
    1.05f, 1.3f, 1.1f, 1.2f, 1.0f, 1.1f, 1.2f, 1.0f, 1.4f, 1.0f,
    1.0f,  1.3f, 1.0f, 1.5f, 1.0f, 1.05f, 1.05f, 1.6f, 1.4f, 1.1f
};

// ---------------- k0: reset replay state -------------------------------------
__global__ void k_init() {
    int t = blockIdx.x * blockDim.x + threadIdx.x;
    if (t < NCELL) g_cellcnt[t] = 0;
    if (t == 0) { g_nfar = 0; g_maxcount = 0; }
}

// ---------------- k1: min dist to ligand, compact far atoms + cell histo -----
__global__ void k_mind(const float* __restrict__ pos,
                       const float* __restrict__ lig,
                       int N, int M) {
    __shared__ float s_lig[3 * 256];
    for (int t = threadIdx.x; t < M * 3; t += blockDim.x) s_lig[t] = lig[t];
    __syncthreads();

    int i = blockIdx.x * blockDim.x + threadIdx.x;
    if (i >= N) return;

    float px = pos[3 * i + 0], py = pos[3 * i + 1], pz = pos[3 * i + 2];
    float best = 3.4e38f;
    for (int m = 0; m < M; m++) {
        float dx = px - s_lig[3 * m + 0];
        float dy = py - s_lig[3 * m + 1];
        float dz = pz - s_lig[3 * m + 2];
        best = fminf(best, dx * dx + dy * dy + dz * dz);
    }
    float d = sqrtf(fmaxf(best, 1e-12f));
    g_mind[i] = d;

    if (d > 8.0f) {
        int cx = min((int)(px * 0.2f), 7);
        int cy = min((int)(py * 0.2f), 7);
        int cz = min((int)(pz * 0.2f), 7);
        int c  = (cz << 6) | (cy << 3) | cx;
        int slot = atomicAdd(&g_nfar, 1);
        g_farpos[slot]  = make_float4(px, py, pz, 0.0f);
        g_faridx[slot]  = i;
        g_farcell[slot] = c;
        atomicAdd(&g_cellcnt[c], 1);
    }
}

// ---------------- k2: exclusive prefix scan over 512 cells (1 block) ---------
__global__ void k_scan() {
    __shared__ int sh[NCELL];
    int t = threadIdx.x;
    int my = g_cellcnt[t];
    sh[t] = my;
    __syncthreads();
    for (int off = 1; off < NCELL; off <<= 1) {
        int add = (t >= off) ? sh[t - off] : 0;
        __syncthreads();
        sh[t] += add;
        __syncthreads();
    }
    int excl = sh[t] - my;
    g_cellstart[t] = excl;
    g_cellfill[t]  = excl;
    if (t == NCELL - 1) g_cellstart[NCELL] = sh[t];
}

// ---------------- k3: scatter far atoms into cell-sorted order ---------------
__global__ void k_scatter() {
    int t = blockIdx.x * blockDim.x + threadIdx.x;
    if (t >= g_nfar) return;
    int c   = g_farcell[t];
    int dst = atomicAdd(&g_cellfill[c], 1);
    g_spos[dst] = g_farpos[t];
    g_sidx[dst] = g_faridx[t];
}

// ---------------- k4: per-cell neighbor counts (27-cell smem neighborhood) ---
__global__ void __launch_bounds__(256) k_counts() {
    __shared__ float4 s_nb[NB_CAP];

    int c  = blockIdx.x;
    int s0 = g_cellstart[c];
    int A  = g_cellstart[c + 1] - s0;
    if (A == 0) return;

    int cx = c & 7, cy = (c >> 3) & 7, cz = c >> 6;

    // gather 27-cell neighborhood into smem
    int T = 0;
    for (int dz = -1; dz <= 1; dz++) {
        int z = cz + dz; if (z < 0 || z > 7) continue;
        for (int dy = -1; dy <= 1; dy++) {
            int y = cy + dy; if (y < 0 || y > 7) continue;
            for (int dx = -1; dx <= 1; dx++) {
                int x = cx + dx; if (x < 0 || x > 7) continue;
                int nc  = (z << 6) | (y << 3) | x;
                int st  = g_cellstart[nc];
                int len = g_cellstart[nc + 1] - st;
                if (T + len > NB_CAP) len = NB_CAP - T;   // safety clamp
                for (int k = threadIdx.x; k < len; k += blockDim.x)
                    s_nb[T + k] = g_spos[st + k];
                T += len;
            }
        }
    }
    __syncthreads();

    // warp per atom, lanes stride over neighborhood
    int warp = threadIdx.x >> 5, lane = threadIdx.x & 31;
    int nwarps = blockDim.x >> 5;
    int wmax = 0;
    for (int a = warp; a < A; a += nwarps) {
        float4 p = g_spos[s0 + a];
        int cnt = 0;
        for (int j = lane; j < T; j += 32) {
            float4 q = s_nb[j];
            float dx = p.x - q.x, dy = p.y - q.y, dz = p.z - q.z;
            float d2 = dx * dx + dy * dy + dz * dz;
            cnt += (d2 < 25.0f && d2 > 0.0f) ? 1 : 0;
        }
        #pragma unroll
        for (int o = 16; o > 0; o >>= 1)
            cnt += __shfl_down_sync(0xffffffffu, cnt, o);
        if (lane == 0) {
            g_counts[g_sidx[s0 + a]] = cnt;
            wmax = max(wmax, cnt);
        }
    }
    if (lane == 0 && wmax > 0) atomicMax(&g_maxcount, wmax);
}

// ---------------- k5: final scores + packed sort keys ------------------------
__global__ void k_score(const float* __restrict__ x,
                        float* __restrict__ out, int N, int F) {
    int i = blockIdx.x * blockDim.x + threadIdx.x;
    if (i >= N) return;

    float d = g_mind[i];
    float s;
    if (d <= 3.5f) {
        s = 10.0f;
    } else if (d <= 8.0f) {
        s = 5.0f * (8.0f - d) / 8.0f;
    } else {
        float mx = (float)g_maxcount;
        mx = (mx > 0.0f) ? mx : 1.0f;
        s = 1.0f - (float)g_counts[i] / (mx + 1e-6f);
    }
    int rt = (int)x[i * F + 1];
    rt = min(max(rt, 0), 19);
    s *= c_bond[rt];

    out[i] = s;

    unsigned int b = __float_as_uint(s);
    unsigned int u = b ^ ((b >> 31) ? 0xFFFFFFFFu : 0x80000000u);  // order-preserving
    g_keys[i] = ((unsigned long long)u << 32) | (unsigned long long)(0xFFFFFFFFu - (unsigned)i);
}

// ---------------- k6: per-block bitonic sort of 512 (descending) -------------
__global__ void k_sort512(int N) {
    __shared__ unsigned long long s[RUN];
    int t = threadIdx.x;
    int g = blockIdx.x * RUN + t;
    s[t] = (g < N) ? g_keys[g] : 0ULL;
    __syncthreads();

    for (int k = 2; k <= RUN; k <<= 1) {
        for (int j = k >> 1; j > 0; j >>= 1) {
            int ixj = t ^ j;
            if (ixj > t) {
                unsigned long long a = s[t], c = s[ixj];
                bool descRegion = ((t & k) == 0);
                if (descRegion ? (a < c) : (a > c)) { s[t] = c; s[ixj] = a; }
            }
            __syncthreads();
        }
    }
    g_runsA[blockIdx.x * RUN + t] = s[t];
}

// ---------------- k7: merge two desc runs of 512, keep top 512 ---------------
__global__ void k_merge(int srcIsA) {
    const unsigned long long* src = srcIsA ? g_runsA : g_runsB;
    unsigned long long*       dst = srcIsA ? g_runsB : g_runsA;

    __shared__ unsigned long long s[2 * RUN];
    int t = threadIdx.x;
    int b = blockIdx.x;
    s[t]       = src[(2 * b)     * RUN + t];
    s[RUN + t] = src[(2 * b + 1) * RUN + (RUN - 1 - t)];  // reversed -> bitonic
    __syncthreads();

    for (int j = RUN; j > 0; j >>= 1) {
        int i = ((t & ~(j - 1)) << 1) | (t & (j - 1));
        int p = i | j;
        unsigned long long a = s[i], c = s[p];
        if (a < c) { s[i] = c; s[p] = a; }
        __syncthreads();
    }
    dst[b * RUN + t] = s[t];
}

// ---------------- k8: unpack and write top-K scores + indices ----------------
__global__ void k_write(int finalInA, float* __restrict__ out, int N, int K) {
    const unsigned long long* run = finalInA ? g_runsA : g_runsB;
    int t = blockIdx.x * blockDim.x + threadIdx.x;
    if (t >= K) return;
    unsigned long long key = run[t];
    unsigned int u = (unsigned int)(key >> 32);
    unsigned int b = (u >> 31) ? (u ^ 0x80000000u) : (~u);
    float sc = __uint_as_float(b);
    unsigned int idx = 0xFFFFFFFFu - (unsigned int)(key & 0xFFFFFFFFull);
    out[N + t]     = sc;
    out[N + K + t] = (float)idx;
}

// ---------------- launch ------------------------------------------------------
extern "C" void kernel_launch(void* const* d_in, const int* in_sizes, int n_in,
                              void* d_out, int out_size) {
    const float* pos = (const float*)d_in[0];
    const float* lig = (const float*)d_in[1];
    const float* x   = (const float*)d_in[2];
    int N = in_sizes[0] / 3;          // 16384
    int M = in_sizes[1] / 3;          // 64
    int F = in_sizes[2] / N;          // 16
    int K = (out_size - N) / 2;       // 512
    float* out = (float*)d_out;

    k_init<<<2, 256>>>();
    k_mind<<<(N + 255) / 256, 256>>>(pos, lig, N, M);
    k_scan<<<1, NCELL>>>();
    k_scatter<<<(N + 255) / 256, 256>>>();
    k_counts<<<NCELL, 256>>>();
    k_score<<<(N + 255) / 256, 256>>>(x, out, N, F);

    int runs = (N + RUN - 1) / RUN;   // 32
    k_sort512<<<runs, RUN>>>(N);

    int srcA = 1;
    while (runs > 1) {
        k_merge<<<runs / 2, RUN>>>(srcA);
        srcA ^= 1;
        runs >>= 1;
    }
    k_write<<<(K + 255) / 256, 256>>>(srcA, out, N, K);
}

// round 3
// speedup vs baseline: 6.4647x; 1.2429x over previous
#include <cuda_runtime.h>
#include <cstdint>

typedef unsigned long long u64;

#define MAXN   16384
#define RUN    512
#define NCELL  512           // 8x8x8 cells of 5 Angstrom
#define CAP    128           // bucket capacity per cell (expected ~32)
#define NB_CAP 2560          // smem neighborhood capacity (float4) = 40KB

// ---------------- scratch (device globals, zero-initialized at load) --------
__device__ float  g_mind[MAXN];
__device__ int    g_counts[MAXN];          // only far atoms' entries read
__device__ int    g_cellcnt[NCELL];        // reset by k_sortscore each run
__device__ float4 g_bucket[NCELL * CAP];   // per-cell far-atom positions
__device__ int    g_bucketidx[NCELL * CAP];
__device__ int    g_maxcount;              // reset by k_merge_final each run
__device__ u64    g_runsA[MAXN];
__device__ u64    g_runsB[MAXN];

__constant__ float c_bond[20] = {
    1.05f, 1.3f, 1.1f, 1.2f, 1.0f, 1.1f, 1.2f, 1.0f, 1.4f, 1.0f,
    1.0f,  1.3f, 1.0f, 1.5f, 1.0f, 1.05f, 1.05f, 1.6f, 1.4f, 1.1f
};

// ---------------- k1: min dist to ligand + direct bucket scatter -------------
__global__ void k_mind(const float* __restrict__ pos,
                       const float* __restrict__ lig,
                       int N, int M) {
    __shared__ float s_lig[3 * 256];
    for (int t = threadIdx.x; t < M * 3; t += blockDim.x) s_lig[t] = lig[t];
    __syncthreads();

    int i = blockIdx.x * blockDim.x + threadIdx.x;
    if (i >= N) return;

    float px = pos[3 * i + 0], py = pos[3 * i + 1], pz = pos[3 * i + 2];
    float best = 3.4e38f;
    for (int m = 0; m < M; m++) {
        float dx = px - s_lig[3 * m + 0];
        float dy = py - s_lig[3 * m + 1];
        float dz = pz - s_lig[3 * m + 2];
        best = fminf(best, dx * dx + dy * dy + dz * dz);
    }
    float d = sqrtf(fmaxf(best, 1e-12f));
    g_mind[i] = d;

    if (d > 8.0f) {
        int cx = min((int)(px * 0.2f), 7);
        int cy = min((int)(py * 0.2f), 7);
        int cz = min((int)(pz * 0.2f), 7);
        int c  = (cz << 6) | (cy << 3) | cx;
        int r  = atomicAdd(&g_cellcnt[c], 1);
        if (r < CAP) {
            g_bucket[c * CAP + r]    = make_float4(px, py, pz, 0.0f);
            g_bucketidx[c * CAP + r] = i;
        }
    }
}

// ---------------- k2: per-cell neighbor counts (27-cell smem gather) ---------
__global__ void __launch_bounds__(256) k_counts() {
    __shared__ float4 s_nb[NB_CAP];

    int c = blockIdx.x;
    int A = min(g_cellcnt[c], CAP);
    if (A == 0) return;

    int cx = c & 7, cy = (c >> 3) & 7, cz = c >> 6;

    int T = 0, T0 = 0;
    for (int dz = -1; dz <= 1; dz++) {
        int z = cz + dz; if (z < 0 || z > 7) continue;
        for (int dy = -1; dy <= 1; dy++) {
            int y = cy + dy; if (y < 0 || y > 7) continue;
            for (int dx = -1; dx <= 1; dx++) {
                int x = cx + dx; if (x < 0 || x > 7) continue;
                int nc  = (z << 6) | (y << 3) | x;
                int len = min(g_cellcnt[nc], CAP);
                if (T + len > NB_CAP) len = NB_CAP - T;  // safety clamp
                if (nc == c) T0 = T;
                for (int k = threadIdx.x; k < len; k += blockDim.x)
                    s_nb[T + k] = g_bucket[nc * CAP + k];
                T += len;
            }
        }
    }
    __syncthreads();

    int warp = threadIdx.x >> 5, lane = threadIdx.x & 31;
    int nwarps = blockDim.x >> 5;
    int wmax = 0;
    for (int a = warp; a < A; a += nwarps) {
        float4 p = s_nb[T0 + a];
        int cnt = 0;
        for (int j = lane; j < T; j += 32) {
            float4 q = s_nb[j];
            float dx = p.x - q.x, dy = p.y - q.y, dz = p.z - q.z;
            float d2 = dx * dx + dy * dy + dz * dz;
            cnt += (d2 < 25.0f && d2 > 0.0f) ? 1 : 0;
        }
        #pragma unroll
        for (int o = 16; o > 0; o >>= 1)
            cnt += __shfl_down_sync(0xffffffffu, cnt, o);
        if (lane == 0) {
            g_counts[g_bucketidx[c * CAP + a]] = cnt;
            wmax = max(wmax, cnt);
        }
    }
    if (lane == 0 && wmax > 0) atomicMax(&g_maxcount, wmax);
}

// ---------------- k3: score + key + block bitonic sort of 512 ----------------
__global__ void __launch_bounds__(RUN) k_sortscore(const float* __restrict__ x,
                                                   float* __restrict__ out,
                                                   int N, int F) {
    __shared__ u64 s[RUN];
    int t = threadIdx.x;
    int i = blockIdx.x * RUN + t;

    // self-clean cell counters for next run (k_counts already consumed them)
    if (blockIdx.x == 0 && t < NCELL) g_cellcnt[t] = 0;

    u64 key = 0ULL;
    if (i < N) {
        float d = g_mind[i];
        float sc;
        if (d <= 3.5f) {
            sc = 10.0f;
        } else if (d <= 8.0f) {
            sc = 5.0f * (8.0f - d) / 8.0f;
        } else {
            float mx = (float)g_maxcount;
            mx = (mx > 0.0f) ? mx : 1.0f;
            sc = 1.0f - (float)g_counts[i] / (mx + 1e-6f);
        }
        int rt = (int)x[i * F + 1];
        rt = min(max(rt, 0), 19);
        sc *= c_bond[rt];

        out[i] = sc;

        unsigned int b = __float_as_uint(sc);
        unsigned int u = b ^ ((b >> 31) ? 0xFFFFFFFFu : 0x80000000u);
        key = ((u64)u << 32) | (u64)(0xFFFFFFFFu - (unsigned)i);
    }
    s[t] = key;
    __syncthreads();

    for (int k = 2; k <= RUN; k <<= 1) {
        for (int j = k >> 1; j > 0; j >>= 1) {
            int ixj = t ^ j;
            if (ixj > t) {
                u64 a = s[t], c = s[ixj];
                bool descRegion = ((t & k) == 0);
                if (descRegion ? (a < c) : (a > c)) { s[t] = c; s[ixj] = a; }
            }
            __syncthreads();
        }
    }
    g_runsA[blockIdx.x * RUN + t] = s[t];
}

// ---------------- k4: merge 4 desc runs -> top 512 (1024 threads) ------------
// srcIsA selects g_runsA->g_runsB or g_runsB->g_runsA (globals, no host ptrs).
__global__ void __launch_bounds__(1024) k_merge4(int srcIsA) {
    const u64* src = srcIsA ? g_runsA : g_runsB;
    u64*       dst = srcIsA ? g_runsB : g_runsA;

    __shared__ u64 s[2048];
    int t = threadIdx.x;
    int b = blockIdx.x;
    int half = t >> 9;          // 0 or 1
    int w = t & (RUN - 1);

    // half h merges runs (4b+2h), (4b+2h+1); second run reversed -> bitonic
    s[half * 1024 + w]       = src[(4 * b + 2 * half) * RUN + w];
    s[half * 1024 + RUN + w] = src[(4 * b + 2 * half + 1) * RUN + (RUN - 1 - w)];
    __syncthreads();

    // phase 1: two independent 1024-element bitonic merges (descending)
    for (int j = RUN; j > 0; j >>= 1) {
        int i = half * 1024 + (((w & ~(j - 1)) << 1) | (w & (j - 1)));
        int p = i | j;
        u64 a = s[i], c = s[p];
        if (a < c) { s[i] = c; s[p] = a; }
        __syncthreads();
    }

    // phase 2: merge the two top-512s
    u64 v = 0ULL;
    if (half == 1) v = s[1024 + (RUN - 1 - w)];
    __syncthreads();
    if (half == 1) s[RUN + w] = v;
    __syncthreads();

    for (int j = RUN; j > 0; j >>= 1) {
        if (half == 0) {
            int i = ((w & ~(j - 1)) << 1) | (w & (j - 1));
            int p = i | j;
            u64 a = s[i], c = s[p];
            if (a < c) { s[i] = c; s[p] = a; }
        }
        __syncthreads();
    }
    if (half == 0) dst[b * RUN + w] = s[w];
}

// ---------------- k5: final merge of 2 runs + unpack/write top-K -------------
__global__ void __launch_bounds__(RUN) k_merge_final(float* __restrict__ out,
                                                     int N, int K) {
    __shared__ u64 s[2 * RUN];
    int t = threadIdx.x;
    s[t]       = g_runsA[t];
    s[RUN + t] = g_runsA[RUN + (RUN - 1 - t)];
    __syncthreads();

    for (int j = RUN; j > 0; j >>= 1) {
        int i = ((t & ~(j - 1)) << 1) | (t & (j - 1));
        int p = i | j;
        u64 a = s[i], c = s[p];
        if (a < c) { s[i] = c; s[p] = a; }
        __syncthreads();
    }

    if (t < K) {
        u64 key = s[t];
        unsigned int u = (unsigned int)(key >> 32);
        unsigned int b = (u >> 31) ? (u ^ 0x80000000u) : (~u);
        float sc = __uint_as_float(b);
        unsigned int idx = 0xFFFFFFFFu - (unsigned int)(key & 0xFFFFFFFFull);
        out[N + t]     = sc;
        out[N + K + t] = (float)idx;
    }
    if (t == 0) g_maxcount = 0;   // self-clean for next run
}

// ---------------- launch ------------------------------------------------------
extern "C" void kernel_launch(void* const* d_in, const int* in_sizes, int n_in,
                              void* d_out, int out_size) {
    const float* pos = (const float*)d_in[0];
    const float* lig = (const float*)d_in[1];
    const float* x   = (const float*)d_in[2];
    int N = in_sizes[0] / 3;          // 16384
    int M = in_sizes[1] / 3;          // 64
    int F = in_sizes[2] / N;          // 16
    int K = (out_size - N) / 2;       // 512
    float* out = (float*)d_out;

    k_mind<<<(N + 255) / 256, 256>>>(pos, lig, N, M);
    k_counts<<<NCELL, 256>>>();
    k_sortscore<<<(N + RUN - 1) / RUN, RUN>>>(x, out, N, F);   // 32 runs -> g_runsA
    k_merge4<<<8, 1024>>>(1);        // A(32) -> B(8)
    k_merge4<<<2, 1024>>>(0);        // B(8)  -> A(2)
    k_merge_final<<<1, RUN>>>(out, N, K);   // A(2) -> out
}